// round 13
// baseline (speedup 1.0000x reference)
#include <cuda_runtime.h>
#include <cuda_fp16.h>
#include <mma.h>
#include <cstdint>

using namespace nvcuda;

#define IN_FEAT   64
#define OUT_FEAT  64
#define MAX_NODES 100000
#define MAX_EDGES 1600000
#define NB_SCAN   ((MAX_NODES + 255) / 256)   // 391

#define SA_LD 72
#define SC_LD 68

// Scratch (__device__ globals: allocation-free, zero-initialized at load)
__device__ __half2      g_h16[MAX_NODES * 32];   // h in fp16 (12.8 MB)
__device__ int          g_cnt[MAX_NODES];        // histogram (zero-invariant)
__device__ int          g_off[MAX_NODES + 1];    // CSR offsets
__device__ int          g_rank[MAX_EDGES];       // per-edge rank within its dst
__device__ int          g_bsum[NB_SCAN];         // scan block sums
__device__ int2         g_pair[MAX_EDGES];       // dst-sorted (src, att)
__device__ unsigned int g_barCount = 0;          // grid barrier state
__device__ unsigned int g_barGen   = 0;

// ---------------------------------------------------------------------------
// Kernel 1: h = feat @ W + b -> fp16, via HMMA (unchanged, measured ~8-9us)
// ---------------------------------------------------------------------------
__global__ __launch_bounds__(256) void gemm_kernel(
    const float* __restrict__ feat,
    const float* __restrict__ W,
    const float* __restrict__ bias,
    int n_nodes)
{
    extern __shared__ char smem[];
    __half (*sA)[SA_LD] = reinterpret_cast<__half(*)[SA_LD]>(smem);
    __half (*sB)[SA_LD] = reinterpret_cast<__half(*)[SA_LD]>(smem + 128 * SA_LD * 2);
    float*  sBias       = reinterpret_cast<float*>(smem + (128 + 64) * SA_LD * 2);
    float (*sC)[16][SC_LD] =
        reinterpret_cast<float(*)[16][SC_LD]>(smem + (128 + 64) * SA_LD * 2 + 256);

    const int tid  = threadIdx.x;
    const int row0 = blockIdx.x * 128;

    {
        int k = tid >> 2, c4 = tid & 3;
        const float4* ws = reinterpret_cast<const float4*>(W + k * OUT_FEAT + c4 * 16);
#pragma unroll
        for (int i = 0; i < 4; i++) {
            float4 v = ws[i];
            int c = c4 * 16 + i * 4;
            sB[k][c + 0] = __float2half(v.x); sB[k][c + 1] = __float2half(v.y);
            sB[k][c + 2] = __float2half(v.z); sB[k][c + 3] = __float2half(v.w);
        }
    }
    if (tid < OUT_FEAT) sBias[tid] = bias[tid];

    {
        int rl = tid >> 1, hf = tid & 1;
        int grow = row0 + rl;
        const float* fr = feat + (size_t)grow * IN_FEAT + hf * 32;
#pragma unroll
        for (int i = 0; i < 8; i++) {
            float4 v = (grow < n_nodes)
                ? *reinterpret_cast<const float4*>(fr + i * 4)
                : make_float4(0.f, 0.f, 0.f, 0.f);
            int c = hf * 32 + i * 4;
            sA[rl][c + 0] = __float2half(v.x); sA[rl][c + 1] = __float2half(v.y);
            sA[rl][c + 2] = __float2half(v.z); sA[rl][c + 3] = __float2half(v.w);
        }
    }
    __syncthreads();

    const int w    = tid >> 5;
    const int lane = tid & 31;

    wmma::fragment<wmma::accumulator, 16, 16, 16, float> c[4];
#pragma unroll
    for (int n = 0; n < 4; n++) wmma::fill_fragment(c[n], 0.0f);

#pragma unroll
    for (int k = 0; k < 4; k++) {
        wmma::fragment<wmma::matrix_a, 16, 16, 16, __half, wmma::row_major> a;
        wmma::load_matrix_sync(a, &sA[w * 16][k * 16], SA_LD);
#pragma unroll
        for (int n = 0; n < 4; n++) {
            wmma::fragment<wmma::matrix_b, 16, 16, 16, __half, wmma::row_major> b;
            wmma::load_matrix_sync(b, &sB[k * 16][n * 16], SA_LD);
            wmma::mma_sync(c[n], a, b, c[n]);
        }
    }
#pragma unroll
    for (int n = 0; n < 4; n++)
        wmma::store_matrix_sync(&sC[w][0][n * 16], c[n], SC_LD, wmma::mem_row_major);
    __syncwarp();

    int rr = lane >> 1, hf = lane & 1;
    int grow = row0 + w * 16 + rr;
    if (grow < n_nodes) {
#pragma unroll
        for (int i = 0; i < 8; i++) {
            int col = hf * 32 + i * 4;
            float x0 = sC[w][rr][col + 0] + sBias[col + 0];
            float x1 = sC[w][rr][col + 1] + sBias[col + 1];
            float x2 = sC[w][rr][col + 2] + sBias[col + 2];
            float x3 = sC[w][rr][col + 3] + sBias[col + 3];
            __half2 p0 = __floats2half2_rn(x0, x1);
            __half2 p1 = __floats2half2_rn(x2, x3);
            uint2 u;
            u.x = *reinterpret_cast<uint32_t*>(&p0);
            u.y = *reinterpret_cast<uint32_t*>(&p1);
            *reinterpret_cast<uint2*>(g_h16 + (size_t)grow * 32 + col / 2) = u;
        }
    }
}

#define GEMM_SMEM ((128 + 64) * SA_LD * 2 + 256 + 8 * 16 * SC_LD * 4)

// ---------------------------------------------------------------------------
// Software grid barrier. SAFE ONLY because grid size == resident capacity
// (host sizes the grid from the occupancy API). Generation counter survives
// graph replays (compared against a locally captured value).
// ---------------------------------------------------------------------------
__device__ __forceinline__ void grid_barrier(int nblocks)
{
    __syncthreads();
    if (threadIdx.x == 0) {
        unsigned int gen = *(volatile unsigned int*)&g_barGen;  // read BEFORE arrive
        __threadfence();
        if (atomicAdd(&g_barCount, 1u) == (unsigned int)nblocks - 1u) {
            atomicExch(&g_barCount, 0u);
            __threadfence();
            atomicExch(&g_barGen, gen + 1u);
        } else {
            while (*(volatile unsigned int*)&g_barGen == gen) __nanosleep(64);
        }
        __threadfence();
    }
    __syncthreads();
}

// ---------------------------------------------------------------------------
// Persistent fused kernel: hist -> scanA -> scanB -> perm -> accum,
// separated by grid barriers instead of kernel launches.
// ---------------------------------------------------------------------------
__global__ __launch_bounds__(256, 4) void fused_kernel(
    const float* __restrict__ att,
    const int*   __restrict__ src,
    const int*   __restrict__ dst,
    float*       __restrict__ out,
    int n_nodes, int n_edges, int nblocks)
{
    __shared__ int wsum[8];
    const int tid  = threadIdx.x;
    const int lane = tid & 31;
    const int wid  = tid >> 5;

    // ---------- Phase 0: hist (4 edges/thread, rank = atomicAdd return) ----
    {
        int chunks4 = (n_edges + 3) / 4;
        for (int v = blockIdx.x * 256 + tid; v < chunks4; v += nblocks * 256) {
            int e = v * 4;
            if (e + 3 < n_edges) {
                int4 d = *reinterpret_cast<const int4*>(dst + e);
                int4 r;
                r.x = atomicAdd(&g_cnt[d.x], 1);
                r.y = atomicAdd(&g_cnt[d.y], 1);
                r.z = atomicAdd(&g_cnt[d.z], 1);
                r.w = atomicAdd(&g_cnt[d.w], 1);
                *reinterpret_cast<int4*>(g_rank + e) = r;
            } else {
                for (; e < n_edges; e++)
                    g_rank[e] = atomicAdd(&g_cnt[dst[e]], 1);
            }
        }
    }
    grid_barrier(nblocks);

    // ---------- Phase 1: scanA — block-local exclusive scan per 256-chunk --
    {
        int nodeChunks = (n_nodes + 255) / 256;
        for (int c = blockIdx.x; c < nodeChunks; c += nblocks) {
            __syncthreads();                      // protect wsum reuse
            int i = c * 256 + tid;
            int v = (i < n_nodes) ? g_cnt[i] : 0;
            if (i < n_nodes) g_cnt[i] = 0;        // restore zero-invariant

            int x = v;
#pragma unroll
            for (int off = 1; off < 32; off <<= 1) {
                int t = __shfl_up_sync(0xffffffff, x, off);
                if (lane >= off) x += t;
            }
            if (lane == 31) wsum[wid] = x;
            __syncthreads();
            if (wid == 0) {
                int s = (lane < 8) ? wsum[lane] : 0;
#pragma unroll
                for (int off = 1; off < 8; off <<= 1) {
                    int t = __shfl_up_sync(0xffffffff, s, off);
                    if (lane >= off) s += t;
                }
                if (lane < 8) wsum[lane] = s;
            }
            __syncthreads();
            int incl = x + (wid > 0 ? wsum[wid - 1] : 0);
            if (i < n_nodes) g_off[i] = incl - v;
            if (tid == 255) g_bsum[c] = incl;
        }
    }
    grid_barrier(nblocks);

    // ---------- Phase 2: scanB — redundant prefix reduce + apply -----------
    {
        int nodeChunks = (n_nodes + 255) / 256;
        for (int c = blockIdx.x; c < nodeChunks; c += nblocks) {
            __syncthreads();
            int local = 0;
            for (int t = tid; t < c; t += 256) local += g_bsum[t];
#pragma unroll
            for (int o = 16; o > 0; o >>= 1)
                local += __shfl_down_sync(0xffffffff, local, o);
            if (lane == 0) wsum[wid] = local;
            __syncthreads();
            int prefix;
            {
                int s = (tid < 8) ? wsum[tid] : 0;
                if (wid == 0) {
#pragma unroll
                    for (int o = 4; o > 0; o >>= 1)
                        s += __shfl_down_sync(0xffffffff, s, o);
                    if (lane == 0) wsum[0] = s;
                }
                __syncthreads();
                prefix = wsum[0];
            }
            int i = c * 256 + tid;
            if (i < n_nodes) g_off[i] += prefix;
        }
        if (blockIdx.x == 0 && tid == 0) g_off[n_nodes] = n_edges;
    }
    grid_barrier(nblocks);

    // ---------- Phase 3: perm — atomic-free placement, 4 edges/thread ------
    {
        int chunks4 = (n_edges + 3) / 4;
        for (int v = blockIdx.x * 256 + tid; v < chunks4; v += nblocks * 256) {
            int e = v * 4;
            if (e + 3 < n_edges) {
                int4   s = *reinterpret_cast<const int4*>(src + e);
                int4   d = *reinterpret_cast<const int4*>(dst + e);
                int4   r = *reinterpret_cast<const int4*>(g_rank + e);
                float4 a = *reinterpret_cast<const float4*>(att + e);
                g_pair[g_off[d.x] + r.x] = make_int2(s.x, __float_as_int(a.x));
                g_pair[g_off[d.y] + r.y] = make_int2(s.y, __float_as_int(a.y));
                g_pair[g_off[d.z] + r.z] = make_int2(s.z, __float_as_int(a.z));
                g_pair[g_off[d.w] + r.w] = make_int2(s.w, __float_as_int(a.w));
            } else {
                for (; e < n_edges; e++)
                    g_pair[g_off[dst[e]] + g_rank[e]] =
                        make_int2(src[e], __float_as_int(att[e]));
            }
        }
    }
    grid_barrier(nblocks);

    // ---------- Phase 4: accum — warp per node, grid-stride ----------------
    {
        int gwarp      = blockIdx.x * 8 + wid;
        int totalWarps = nblocks * 8;
        for (int node = gwarp; node < n_nodes; node += totalWarps) {
            int j   = g_off[node];
            int end = g_off[node + 1];

            float2 acc = make_float2(0.f, 0.f);
            for (; j + 3 < end; j += 4) {
                int2 p0 = __ldg(&g_pair[j]);
                int2 p1 = __ldg(&g_pair[j + 1]);
                int2 p2 = __ldg(&g_pair[j + 2]);
                int2 p3 = __ldg(&g_pair[j + 3]);
                float2 v0 = __half22float2(__ldg(g_h16 + (size_t)p0.x * 32 + lane));
                float2 v1 = __half22float2(__ldg(g_h16 + (size_t)p1.x * 32 + lane));
                float2 v2 = __half22float2(__ldg(g_h16 + (size_t)p2.x * 32 + lane));
                float2 v3 = __half22float2(__ldg(g_h16 + (size_t)p3.x * 32 + lane));
                float a0 = __int_as_float(p0.y), a1 = __int_as_float(p1.y);
                float a2 = __int_as_float(p2.y), a3 = __int_as_float(p3.y);
                acc.x = fmaf(a0, v0.x, acc.x); acc.y = fmaf(a0, v0.y, acc.y);
                acc.x = fmaf(a1, v1.x, acc.x); acc.y = fmaf(a1, v1.y, acc.y);
                acc.x = fmaf(a2, v2.x, acc.x); acc.y = fmaf(a2, v2.y, acc.y);
                acc.x = fmaf(a3, v3.x, acc.x); acc.y = fmaf(a3, v3.y, acc.y);
            }
            for (; j < end; j++) {
                int2 p = __ldg(&g_pair[j]);
                float a = __int_as_float(p.y);
                float2 v = __half22float2(__ldg(g_h16 + (size_t)p.x * 32 + lane));
                acc.x = fmaf(a, v.x, acc.x);
                acc.y = fmaf(a, v.y, acc.y);
            }
            *reinterpret_cast<float2*>(out + (size_t)node * OUT_FEAT + lane * 2) = acc;
        }
    }
}

// ---------------------------------------------------------------------------
// Launch: gemm (serial), then ONE persistent kernel for everything else.
// Grid sized to exactly-resident occupancy so the grid barriers cannot hang.
// ---------------------------------------------------------------------------
extern "C" void kernel_launch(void* const* d_in, const int* in_sizes, int n_in,
                              void* d_out, int out_size)
{
    const float* feat = (const float*)d_in[0];
    const float* att  = (const float*)d_in[1];
    const int*   src  = (const int*)  d_in[2];
    const int*   dst  = (const int*)  d_in[3];
    const float* W    = (const float*)d_in[4];
    const float* bias = (const float*)d_in[5];
    float*       out  = (float*)d_out;

    int n_nodes = in_sizes[0] / IN_FEAT;
    int n_edges = in_sizes[2];

    cudaFuncSetAttribute(gemm_kernel,
                         cudaFuncAttributeMaxDynamicSharedMemorySize, GEMM_SMEM);

    // size the persistent grid to guaranteed co-residency
    int numSMs = 0, occ = 0;
    cudaDeviceGetAttribute(&numSMs, cudaDevAttrMultiProcessorCount, 0);
    cudaOccupancyMaxActiveBlocksPerMultiprocessor(&occ, fused_kernel, 256, 0);
    if (occ < 1) occ = 1;
    if (occ > 8) occ = 8;
    int nblocks = numSMs * occ;

    // 1) h = feat @ W + b (fp16 to g_h16)
    gemm_kernel<<<(n_nodes + 127) / 128, 256, GEMM_SMEM>>>(feat, W, bias, n_nodes);

    // 2) everything else in one persistent kernel
    fused_kernel<<<nblocks, 256>>>(att, src, dst, out, n_nodes, n_edges, nblocks);
}

// round 15
// speedup vs baseline: 1.0825x; 1.0825x over previous
#include <cuda_runtime.h>
#include <cuda_fp16.h>
#include <mma.h>
#include <cstdint>

using namespace nvcuda;

#define IN_FEAT   64
#define OUT_FEAT  64
#define MAX_NODES 100000
#define MAX_EDGES 1600000
#define NB_SCAN   ((MAX_NODES + 255) / 256)   // 391

#define SA_LD 72
#define SC_LD 68

// Scratch (__device__ globals: allocation-free, zero-initialized at load)
__device__ __half2 g_h16[MAX_NODES * 32];   // h in fp16 (12.8 MB)
__device__ int     g_cnt[MAX_NODES];        // histogram (zero-invariant)
__device__ int     g_off[MAX_NODES];        // CSR offsets, BLOCK-LOCAL exclusive
__device__ int     g_rank[MAX_EDGES];       // per-edge rank within its dst
__device__ int     g_bsum[NB_SCAN];         // per-chunk totals
__device__ int2    g_pair[MAX_EDGES];       // dst-sorted (src, att)

// ---------------------------------------------------------------------------
// Kernel 1: h = feat @ W + b -> fp16, via HMMA (measured ~8-9us)
// ---------------------------------------------------------------------------
__global__ __launch_bounds__(256) void gemm_kernel(
    const float* __restrict__ feat,
    const float* __restrict__ W,
    const float* __restrict__ bias,
    int n_nodes)
{
    extern __shared__ char smem[];
    __half (*sA)[SA_LD] = reinterpret_cast<__half(*)[SA_LD]>(smem);
    __half (*sB)[SA_LD] = reinterpret_cast<__half(*)[SA_LD]>(smem + 128 * SA_LD * 2);
    float*  sBias       = reinterpret_cast<float*>(smem + (128 + 64) * SA_LD * 2);
    float (*sC)[16][SC_LD] =
        reinterpret_cast<float(*)[16][SC_LD]>(smem + (128 + 64) * SA_LD * 2 + 256);

    const int tid  = threadIdx.x;
    const int row0 = blockIdx.x * 128;

    {
        int k = tid >> 2, c4 = tid & 3;
        const float4* ws = reinterpret_cast<const float4*>(W + k * OUT_FEAT + c4 * 16);
#pragma unroll
        for (int i = 0; i < 4; i++) {
            float4 v = ws[i];
            int c = c4 * 16 + i * 4;
            sB[k][c + 0] = __float2half(v.x); sB[k][c + 1] = __float2half(v.y);
            sB[k][c + 2] = __float2half(v.z); sB[k][c + 3] = __float2half(v.w);
        }
    }
    if (tid < OUT_FEAT) sBias[tid] = bias[tid];

    {
        int rl = tid >> 1, hf = tid & 1;
        int grow = row0 + rl;
        const float* fr = feat + (size_t)grow * IN_FEAT + hf * 32;
#pragma unroll
        for (int i = 0; i < 8; i++) {
            float4 v = (grow < n_nodes)
                ? *reinterpret_cast<const float4*>(fr + i * 4)
                : make_float4(0.f, 0.f, 0.f, 0.f);
            int c = hf * 32 + i * 4;
            sA[rl][c + 0] = __float2half(v.x); sA[rl][c + 1] = __float2half(v.y);
            sA[rl][c + 2] = __float2half(v.z); sA[rl][c + 3] = __float2half(v.w);
        }
    }
    __syncthreads();

    const int w    = tid >> 5;
    const int lane = tid & 31;

    wmma::fragment<wmma::accumulator, 16, 16, 16, float> c[4];
#pragma unroll
    for (int n = 0; n < 4; n++) wmma::fill_fragment(c[n], 0.0f);

#pragma unroll
    for (int k = 0; k < 4; k++) {
        wmma::fragment<wmma::matrix_a, 16, 16, 16, __half, wmma::row_major> a;
        wmma::load_matrix_sync(a, &sA[w * 16][k * 16], SA_LD);
#pragma unroll
        for (int n = 0; n < 4; n++) {
            wmma::fragment<wmma::matrix_b, 16, 16, 16, __half, wmma::row_major> b;
            wmma::load_matrix_sync(b, &sB[k * 16][n * 16], SA_LD);
            wmma::mma_sync(c[n], a, b, c[n]);
        }
    }
#pragma unroll
    for (int n = 0; n < 4; n++)
        wmma::store_matrix_sync(&sC[w][0][n * 16], c[n], SC_LD, wmma::mem_row_major);
    __syncwarp();

    int rr = lane >> 1, hf = lane & 1;
    int grow = row0 + w * 16 + rr;
    if (grow < n_nodes) {
#pragma unroll
        for (int i = 0; i < 8; i++) {
            int col = hf * 32 + i * 4;
            float x0 = sC[w][rr][col + 0] + sBias[col + 0];
            float x1 = sC[w][rr][col + 1] + sBias[col + 1];
            float x2 = sC[w][rr][col + 2] + sBias[col + 2];
            float x3 = sC[w][rr][col + 3] + sBias[col + 3];
            __half2 p0 = __floats2half2_rn(x0, x1);
            __half2 p1 = __floats2half2_rn(x2, x3);
            uint2 u;
            u.x = *reinterpret_cast<uint32_t*>(&p0);
            u.y = *reinterpret_cast<uint32_t*>(&p1);
            *reinterpret_cast<uint2*>(g_h16 + (size_t)grow * 32 + col / 2) = u;
        }
    }
}

#define GEMM_SMEM ((128 + 64) * SA_LD * 2 + 256 + 8 * 16 * SC_LD * 4)

// ---------------------------------------------------------------------------
// Shared helper: inclusive Hillis-Steele scan of g_bsum into sS[512].
// base(chunk) = chunk ? sS[chunk-1] : 0.
// ---------------------------------------------------------------------------
__device__ __forceinline__ void chunk_prefix_scan(int* sS, int nchunks)
{
    int t = threadIdx.x;
    sS[t]       = (t       < nchunks) ? g_bsum[t]       : 0;
    sS[t + 256] = (t + 256 < nchunks) ? g_bsum[t + 256] : 0;
    __syncthreads();
#pragma unroll
    for (int off = 1; off < 512; off <<= 1) {
        int v0 = (t       >= off) ? sS[t - off]       : 0;
        int v1 = (t + 256 >= off) ? sS[t + 256 - off] : 0;
        __syncthreads();
        sS[t] += v0;
        sS[t + 256] += v1;
        __syncthreads();
    }
}

// ---------------------------------------------------------------------------
// hist: 4 edges/thread (int4), rank = atomicAdd return value.
// ---------------------------------------------------------------------------
__global__ void hist_kernel(const int* __restrict__ dst, int n_edges)
{
    int e = (blockIdx.x * blockDim.x + threadIdx.x) * 4;
    if (e + 3 < n_edges) {
        int4 d = *reinterpret_cast<const int4*>(dst + e);
        int4 r;
        r.x = atomicAdd(&g_cnt[d.x], 1);
        r.y = atomicAdd(&g_cnt[d.y], 1);
        r.z = atomicAdd(&g_cnt[d.z], 1);
        r.w = atomicAdd(&g_cnt[d.w], 1);
        *reinterpret_cast<int4*>(g_rank + e) = r;
    } else {
        for (; e < n_edges; e++)
            g_rank[e] = atomicAdd(&g_cnt[dst[e]], 1);
    }
}

// ---------------------------------------------------------------------------
// scan1: per-chunk exclusive scan of g_cnt -> g_off (block-LOCAL),
//        chunk totals -> g_bsum, re-zero g_cnt (restores invariant).
// ---------------------------------------------------------------------------
__global__ __launch_bounds__(256) void scan1_kernel(int n)
{
    __shared__ int wsum[8];
    int i    = blockIdx.x * 256 + threadIdx.x;
    int lane = threadIdx.x & 31;
    int wid  = threadIdx.x >> 5;
    int v    = (i < n) ? g_cnt[i] : 0;
    if (i < n) g_cnt[i] = 0;

    int x = v;
#pragma unroll
    for (int off = 1; off < 32; off <<= 1) {
        int t = __shfl_up_sync(0xffffffff, x, off);
        if (lane >= off) x += t;
    }
    if (lane == 31) wsum[wid] = x;
    __syncthreads();
    if (wid == 0) {
        int s = (lane < 8) ? wsum[lane] : 0;
#pragma unroll
        for (int off = 1; off < 8; off <<= 1) {
            int t = __shfl_up_sync(0xffffffff, s, off);
            if (lane >= off) s += t;
        }
        if (lane < 8) wsum[lane] = s;
    }
    __syncthreads();
    int incl = x + (wid > 0 ? wsum[wid - 1] : 0);
    if (i < n) g_off[i] = incl - v;       // block-local exclusive
    if (threadIdx.x == 255) g_bsum[blockIdx.x] = incl;
}

// ---------------------------------------------------------------------------
// perm: atomic-free placement. Global offset = local excl + smem chunk prefix.
// ---------------------------------------------------------------------------
__global__ __launch_bounds__(256) void perm_kernel(
    const int* __restrict__ src,
    const int* __restrict__ dst,
    const float* __restrict__ att,
    int n_edges, int nchunks)
{
    __shared__ int sS[512];
    chunk_prefix_scan(sS, nchunks);

    int e = (blockIdx.x * blockDim.x + threadIdx.x) * 4;
    if (e + 3 < n_edges) {
        int4   s = *reinterpret_cast<const int4*>(src + e);
        int4   d = *reinterpret_cast<const int4*>(dst + e);
        int4   r = *reinterpret_cast<const int4*>(g_rank + e);
        float4 a = *reinterpret_cast<const float4*>(att + e);
        int b0 = (d.x >> 8) ? sS[(d.x >> 8) - 1] : 0;
        int b1 = (d.y >> 8) ? sS[(d.y >> 8) - 1] : 0;
        int b2 = (d.z >> 8) ? sS[(d.z >> 8) - 1] : 0;
        int b3 = (d.w >> 8) ? sS[(d.w >> 8) - 1] : 0;
        g_pair[g_off[d.x] + b0 + r.x] = make_int2(s.x, __float_as_int(a.x));
        g_pair[g_off[d.y] + b1 + r.y] = make_int2(s.y, __float_as_int(a.y));
        g_pair[g_off[d.z] + b2 + r.z] = make_int2(s.z, __float_as_int(a.z));
        g_pair[g_off[d.w] + b3 + r.w] = make_int2(s.w, __float_as_int(a.w));
    } else {
        for (; e < n_edges; e++) {
            int d = dst[e];
            int b = (d >> 8) ? sS[(d >> 8) - 1] : 0;
            g_pair[g_off[d] + b + g_rank[e]] = make_int2(src[e], __float_as_int(att[e]));
        }
    }
}

// ---------------------------------------------------------------------------
// accum: one warp per dst node; lane owns 2 cols; fp32 accumulation.
// Reads g_h16 via the device symbol directly (NOT a host-passed pointer —
// that was the R14 bug).
// ---------------------------------------------------------------------------
__global__ __launch_bounds__(256) void accum_kernel(
    float* __restrict__ out,
    int n_nodes, int n_edges, int nchunks)
{
    __shared__ int sS[512];
    chunk_prefix_scan(sS, nchunks);

    int warp = (blockIdx.x * 256 + threadIdx.x) >> 5;
    int lane = threadIdx.x & 31;
    if (warp >= n_nodes) return;

    int c0 = warp >> 8;
    int j  = g_off[warp] + (c0 ? sS[c0 - 1] : 0);
    int nx  = warp + 1;
    int end = (nx < n_nodes)
        ? g_off[nx] + ((nx >> 8) ? sS[(nx >> 8) - 1] : 0)
        : n_edges;

    const __half2* __restrict__ h16 = g_h16;

    float2 acc = make_float2(0.f, 0.f);

    for (; j + 3 < end; j += 4) {
        int2 p0 = __ldg(&g_pair[j]);
        int2 p1 = __ldg(&g_pair[j + 1]);
        int2 p2 = __ldg(&g_pair[j + 2]);
        int2 p3 = __ldg(&g_pair[j + 3]);
        float2 v0 = __half22float2(__ldg(h16 + (size_t)p0.x * 32 + lane));
        float2 v1 = __half22float2(__ldg(h16 + (size_t)p1.x * 32 + lane));
        float2 v2 = __half22float2(__ldg(h16 + (size_t)p2.x * 32 + lane));
        float2 v3 = __half22float2(__ldg(h16 + (size_t)p3.x * 32 + lane));
        float a0 = __int_as_float(p0.y), a1 = __int_as_float(p1.y);
        float a2 = __int_as_float(p2.y), a3 = __int_as_float(p3.y);
        acc.x = fmaf(a0, v0.x, acc.x); acc.y = fmaf(a0, v0.y, acc.y);
        acc.x = fmaf(a1, v1.x, acc.x); acc.y = fmaf(a1, v1.y, acc.y);
        acc.x = fmaf(a2, v2.x, acc.x); acc.y = fmaf(a2, v2.y, acc.y);
        acc.x = fmaf(a3, v3.x, acc.x); acc.y = fmaf(a3, v3.y, acc.y);
    }
    for (; j < end; j++) {
        int2 p = __ldg(&g_pair[j]);
        float a = __int_as_float(p.y);
        float2 v = __half22float2(__ldg(h16 + (size_t)p.x * 32 + lane));
        acc.x = fmaf(a, v.x, acc.x);
        acc.y = fmaf(a, v.y, acc.y);
    }

    *reinterpret_cast<float2*>(out + (size_t)warp * OUT_FEAT + lane * 2) = acc;
}

// ---------------------------------------------------------------------------
// Launch: side stream = gemm; main = hist -> scan1 -> perm; join -> accum.
// ---------------------------------------------------------------------------
extern "C" void kernel_launch(void* const* d_in, const int* in_sizes, int n_in,
                              void* d_out, int out_size)
{
    const float* feat = (const float*)d_in[0];
    const float* att  = (const float*)d_in[1];
    const int*   src  = (const int*)  d_in[2];
    const int*   dst  = (const int*)  d_in[3];
    const float* W    = (const float*)d_in[4];
    const float* bias = (const float*)d_in[5];
    float*       out  = (float*)d_out;

    int n_nodes = in_sizes[0] / IN_FEAT;
    int n_edges = in_sizes[2];
    int nchunks = (n_nodes + 255) / 256;

    cudaFuncSetAttribute(gemm_kernel,
                         cudaFuncAttributeMaxDynamicSharedMemorySize, GEMM_SMEM);

    cudaStream_t side;
    cudaStreamCreateWithFlags(&side, cudaStreamNonBlocking);
    cudaEvent_t evFork, evJoin;
    cudaEventCreateWithFlags(&evFork, cudaEventDisableTiming);
    cudaEventCreateWithFlags(&evJoin, cudaEventDisableTiming);

    // fork: gemm on side stream
    cudaEventRecord(evFork, 0);
    cudaStreamWaitEvent(side, evFork, 0);
    gemm_kernel<<<(n_nodes + 127) / 128, 256, GEMM_SMEM, side>>>(feat, W, bias, n_nodes);
    cudaEventRecord(evJoin, side);

    // binning chain on main stream
    int vthreads = (n_edges + 3) / 4;
    hist_kernel<<<(vthreads + 255) / 256, 256>>>(dst, n_edges);
    scan1_kernel<<<(n_nodes + 255) / 256, 256>>>(n_nodes);
    perm_kernel<<<(vthreads + 255) / 256, 256>>>(src, dst, att, n_edges, nchunks);

    // join, then accumulate
    cudaStreamWaitEvent(0, evJoin, 0);
    long long work = (long long)n_nodes * 32;
    accum_kernel<<<(int)((work + 255) / 256), 256>>>(out, n_nodes, n_edges, nchunks);
}

// round 17
// speedup vs baseline: 1.2799x; 1.1824x over previous
#include <cuda_runtime.h>
#include <cuda_fp16.h>
#include <mma.h>
#include <cstdint>

using namespace nvcuda;

#define IN_FEAT   64
#define OUT_FEAT  64
#define MAX_NODES 100000
#define MAX_EDGES 1600000
#define NB_SCAN   ((MAX_NODES + 255) / 256)   // 391

#define SA_LD 72
#define SC_LD 68

// Scratch (__device__ globals: allocation-free, zero-initialized at load)
__device__ __half2 g_h16[MAX_NODES * 32];   // h in fp16 (12.8 MB)
__device__ int     g_cnt[MAX_NODES];        // histogram (zero-invariant)
__device__ int     g_off[MAX_NODES];        // CSR offsets, BLOCK-LOCAL exclusive
__device__ int     g_off2[MAX_NODES + 1];   // resolved global offsets (perm writes)
__device__ int     g_rank[MAX_EDGES];       // per-edge rank within its dst
__device__ int     g_bsum[NB_SCAN];         // per-chunk totals
__device__ int2    g_pair[MAX_EDGES];       // dst-sorted (src, att)

// ---------------------------------------------------------------------------
// Kernel 1: h = feat @ W + b -> fp16, via HMMA (measured ~8-9us)
// ---------------------------------------------------------------------------
__global__ __launch_bounds__(256) void gemm_kernel(
    const float* __restrict__ feat,
    const float* __restrict__ W,
    const float* __restrict__ bias,
    int n_nodes)
{
    extern __shared__ char smem[];
    __half (*sA)[SA_LD] = reinterpret_cast<__half(*)[SA_LD]>(smem);
    __half (*sB)[SA_LD] = reinterpret_cast<__half(*)[SA_LD]>(smem + 128 * SA_LD * 2);
    float*  sBias       = reinterpret_cast<float*>(smem + (128 + 64) * SA_LD * 2);
    float (*sC)[16][SC_LD] =
        reinterpret_cast<float(*)[16][SC_LD]>(smem + (128 + 64) * SA_LD * 2 + 256);

    const int tid  = threadIdx.x;
    const int row0 = blockIdx.x * 128;

    {
        int k = tid >> 2, c4 = tid & 3;
        const float4* ws = reinterpret_cast<const float4*>(W + k * OUT_FEAT + c4 * 16);
#pragma unroll
        for (int i = 0; i < 4; i++) {
            float4 v = ws[i];
            int c = c4 * 16 + i * 4;
            sB[k][c + 0] = __float2half(v.x); sB[k][c + 1] = __float2half(v.y);
            sB[k][c + 2] = __float2half(v.z); sB[k][c + 3] = __float2half(v.w);
        }
    }
    if (tid < OUT_FEAT) sBias[tid] = bias[tid];

    {
        int rl = tid >> 1, hf = tid & 1;
        int grow = row0 + rl;
        const float* fr = feat + (size_t)grow * IN_FEAT + hf * 32;
#pragma unroll
        for (int i = 0; i < 8; i++) {
            float4 v = (grow < n_nodes)
                ? *reinterpret_cast<const float4*>(fr + i * 4)
                : make_float4(0.f, 0.f, 0.f, 0.f);
            int c = hf * 32 + i * 4;
            sA[rl][c + 0] = __float2half(v.x); sA[rl][c + 1] = __float2half(v.y);
            sA[rl][c + 2] = __float2half(v.z); sA[rl][c + 3] = __float2half(v.w);
        }
    }
    __syncthreads();

    const int w    = tid >> 5;
    const int lane = tid & 31;

    wmma::fragment<wmma::accumulator, 16, 16, 16, float> c[4];
#pragma unroll
    for (int n = 0; n < 4; n++) wmma::fill_fragment(c[n], 0.0f);

#pragma unroll
    for (int k = 0; k < 4; k++) {
        wmma::fragment<wmma::matrix_a, 16, 16, 16, __half, wmma::row_major> a;
        wmma::load_matrix_sync(a, &sA[w * 16][k * 16], SA_LD);
#pragma unroll
        for (int n = 0; n < 4; n++) {
            wmma::fragment<wmma::matrix_b, 16, 16, 16, __half, wmma::row_major> b;
            wmma::load_matrix_sync(b, &sB[k * 16][n * 16], SA_LD);
            wmma::mma_sync(c[n], a, b, c[n]);
        }
    }
#pragma unroll
    for (int n = 0; n < 4; n++)
        wmma::store_matrix_sync(&sC[w][0][n * 16], c[n], SC_LD, wmma::mem_row_major);
    __syncwarp();

    int rr = lane >> 1, hf = lane & 1;
    int grow = row0 + w * 16 + rr;
    if (grow < n_nodes) {
#pragma unroll
        for (int i = 0; i < 8; i++) {
            int col = hf * 32 + i * 4;
            float x0 = sC[w][rr][col + 0] + sBias[col + 0];
            float x1 = sC[w][rr][col + 1] + sBias[col + 1];
            float x2 = sC[w][rr][col + 2] + sBias[col + 2];
            float x3 = sC[w][rr][col + 3] + sBias[col + 3];
            __half2 p0 = __floats2half2_rn(x0, x1);
            __half2 p1 = __floats2half2_rn(x2, x3);
            uint2 u;
            u.x = *reinterpret_cast<uint32_t*>(&p0);
            u.y = *reinterpret_cast<uint32_t*>(&p1);
            *reinterpret_cast<uint2*>(g_h16 + (size_t)grow * 32 + col / 2) = u;
        }
    }
}

#define GEMM_SMEM ((128 + 64) * SA_LD * 2 + 256 + 8 * 16 * SC_LD * 4)

// ---------------------------------------------------------------------------
// hist: 4 edges/thread (int4), rank = atomicAdd return value.
// ---------------------------------------------------------------------------
__global__ void hist_kernel(const int* __restrict__ dst, int n_edges)
{
    int e = (blockIdx.x * blockDim.x + threadIdx.x) * 4;
    if (e + 3 < n_edges) {
        int4 d = *reinterpret_cast<const int4*>(dst + e);
        int4 r;
        r.x = atomicAdd(&g_cnt[d.x], 1);
        r.y = atomicAdd(&g_cnt[d.y], 1);
        r.z = atomicAdd(&g_cnt[d.z], 1);
        r.w = atomicAdd(&g_cnt[d.w], 1);
        *reinterpret_cast<int4*>(g_rank + e) = r;
    } else {
        for (; e < n_edges; e++)
            g_rank[e] = atomicAdd(&g_cnt[dst[e]], 1);
    }
}

// ---------------------------------------------------------------------------
// scan1: per-chunk exclusive scan of g_cnt -> g_off (block-LOCAL),
//        chunk totals -> g_bsum, re-zero g_cnt (restores invariant).
// ---------------------------------------------------------------------------
__global__ __launch_bounds__(256) void scan1_kernel(int n)
{
    __shared__ int wsum[8];
    int i    = blockIdx.x * 256 + threadIdx.x;
    int lane = threadIdx.x & 31;
    int wid  = threadIdx.x >> 5;
    int v    = (i < n) ? g_cnt[i] : 0;
    if (i < n) g_cnt[i] = 0;

    int x = v;
#pragma unroll
    for (int off = 1; off < 32; off <<= 1) {
        int t = __shfl_up_sync(0xffffffff, x, off);
        if (lane >= off) x += t;
    }
    if (lane == 31) wsum[wid] = x;
    __syncthreads();
    if (wid == 0) {
        int s = (lane < 8) ? wsum[lane] : 0;
#pragma unroll
        for (int off = 1; off < 8; off <<= 1) {
            int t = __shfl_up_sync(0xffffffff, s, off);
            if (lane >= off) s += t;
        }
        if (lane < 8) wsum[lane] = s;
    }
    __syncthreads();
    int incl = x + (wid > 0 ? wsum[wid - 1] : 0);
    if (i < n) g_off[i] = incl - v;       // block-local exclusive
    if (threadIdx.x == 255) g_bsum[blockIdx.x] = incl;
}

// ---------------------------------------------------------------------------
// perm: smem chunk-prefix scan (once per block), atomic-free placement,
// AND first nchunks blocks publish RESOLVED offsets to g_off2 for accum.
// g_off is read-only here; g_off2 is write-only -> no race.
// ---------------------------------------------------------------------------
__global__ __launch_bounds__(256) void perm_kernel(
    const int* __restrict__ src,
    const int* __restrict__ dst,
    const float* __restrict__ att,
    int n_edges, int nchunks, int n_nodes)
{
    __shared__ int sS[512];
    {
        int t = threadIdx.x;
        sS[t]       = (t       < nchunks) ? g_bsum[t]       : 0;
        sS[t + 256] = (t + 256 < nchunks) ? g_bsum[t + 256] : 0;
        __syncthreads();
#pragma unroll
        for (int off = 1; off < 512; off <<= 1) {
            int v0 = (t       >= off) ? sS[t - off]       : 0;
            int v1 = (t + 256 >= off) ? sS[t + 256 - off] : 0;
            __syncthreads();
            sS[t] += v0;
            sS[t + 256] += v1;
            __syncthreads();
        }
    }

    // publish resolved offsets for accum (first nchunks blocks only)
    int b = blockIdx.x;
    if (b < nchunks) {
        int base = b ? sS[b - 1] : 0;
        int i = b * 256 + threadIdx.x;
        if (i < n_nodes) g_off2[i] = g_off[i] + base;
        if (b == 0 && threadIdx.x == 0) g_off2[n_nodes] = n_edges;
    }

    int e = (blockIdx.x * blockDim.x + threadIdx.x) * 4;
    if (e + 3 < n_edges) {
        int4   s = *reinterpret_cast<const int4*>(src + e);
        int4   d = *reinterpret_cast<const int4*>(dst + e);
        int4   r = *reinterpret_cast<const int4*>(g_rank + e);
        float4 a = *reinterpret_cast<const float4*>(att + e);
        int b0 = (d.x >> 8) ? sS[(d.x >> 8) - 1] : 0;
        int b1 = (d.y >> 8) ? sS[(d.y >> 8) - 1] : 0;
        int b2 = (d.z >> 8) ? sS[(d.z >> 8) - 1] : 0;
        int b3 = (d.w >> 8) ? sS[(d.w >> 8) - 1] : 0;
        g_pair[g_off[d.x] + b0 + r.x] = make_int2(s.x, __float_as_int(a.x));
        g_pair[g_off[d.y] + b1 + r.y] = make_int2(s.y, __float_as_int(a.y));
        g_pair[g_off[d.z] + b2 + r.z] = make_int2(s.z, __float_as_int(a.z));
        g_pair[g_off[d.w] + b3 + r.w] = make_int2(s.w, __float_as_int(a.w));
    } else {
        for (; e < n_edges; e++) {
            int d = dst[e];
            int bb = (d >> 8) ? sS[(d >> 8) - 1] : 0;
            g_pair[g_off[d] + bb + g_rank[e]] = make_int2(src[e], __float_as_int(att[e]));
        }
    }
}

// ---------------------------------------------------------------------------
// accum: one warp per dst node; lane owns 2 cols; fp32 accumulation.
// Plain R12 form — reads RESOLVED g_off2, no per-block prologue.
// ---------------------------------------------------------------------------
__global__ __launch_bounds__(256) void accum_kernel(
    float* __restrict__ out,
    int n_nodes)
{
    int warp = (blockIdx.x * 256 + threadIdx.x) >> 5;
    int lane = threadIdx.x & 31;
    if (warp >= n_nodes) return;

    int j   = g_off2[warp];
    int end = g_off2[warp + 1];

    const __half2* __restrict__ h16 = g_h16;

    float2 acc = make_float2(0.f, 0.f);

    for (; j + 3 < end; j += 4) {
        int2 p0 = __ldg(&g_pair[j]);
        int2 p1 = __ldg(&g_pair[j + 1]);
        int2 p2 = __ldg(&g_pair[j + 2]);
        int2 p3 = __ldg(&g_pair[j + 3]);
        float2 v0 = __half22float2(__ldg(h16 + (size_t)p0.x * 32 + lane));
        float2 v1 = __half22float2(__ldg(h16 + (size_t)p1.x * 32 + lane));
        float2 v2 = __half22float2(__ldg(h16 + (size_t)p2.x * 32 + lane));
        float2 v3 = __half22float2(__ldg(h16 + (size_t)p3.x * 32 + lane));
        float a0 = __int_as_float(p0.y), a1 = __int_as_float(p1.y);
        float a2 = __int_as_float(p2.y), a3 = __int_as_float(p3.y);
        acc.x = fmaf(a0, v0.x, acc.x); acc.y = fmaf(a0, v0.y, acc.y);
        acc.x = fmaf(a1, v1.x, acc.x); acc.y = fmaf(a1, v1.y, acc.y);
        acc.x = fmaf(a2, v2.x, acc.x); acc.y = fmaf(a2, v2.y, acc.y);
        acc.x = fmaf(a3, v3.x, acc.x); acc.y = fmaf(a3, v3.y, acc.y);
    }
    for (; j < end; j++) {
        int2 p = __ldg(&g_pair[j]);
        float a = __int_as_float(p.y);
        float2 v = __half22float2(__ldg(h16 + (size_t)p.x * 32 + lane));
        acc.x = fmaf(a, v.x, acc.x);
        acc.y = fmaf(a, v.y, acc.y);
    }

    *reinterpret_cast<float2*>(out + (size_t)warp * OUT_FEAT + lane * 2) = acc;
}

// ---------------------------------------------------------------------------
// Launch: side stream = gemm; main = hist -> scan1 -> perm; join -> accum.
// ---------------------------------------------------------------------------
extern "C" void kernel_launch(void* const* d_in, const int* in_sizes, int n_in,
                              void* d_out, int out_size)
{
    const float* feat = (const float*)d_in[0];
    const float* att  = (const float*)d_in[1];
    const int*   src  = (const int*)  d_in[2];
    const int*   dst  = (const int*)  d_in[3];
    const float* W    = (const float*)d_in[4];
    const float* bias = (const float*)d_in[5];
    float*       out  = (float*)d_out;

    int n_nodes = in_sizes[0] / IN_FEAT;
    int n_edges = in_sizes[2];
    int nchunks = (n_nodes + 255) / 256;

    cudaFuncSetAttribute(gemm_kernel,
                         cudaFuncAttributeMaxDynamicSharedMemorySize, GEMM_SMEM);

    cudaStream_t side;
    cudaStreamCreateWithFlags(&side, cudaStreamNonBlocking);
    cudaEvent_t evFork, evJoin;
    cudaEventCreateWithFlags(&evFork, cudaEventDisableTiming);
    cudaEventCreateWithFlags(&evJoin, cudaEventDisableTiming);

    // fork: gemm on side stream
    cudaEventRecord(evFork, 0);
    cudaStreamWaitEvent(side, evFork, 0);
    gemm_kernel<<<(n_nodes + 127) / 128, 256, GEMM_SMEM, side>>>(feat, W, bias, n_nodes);
    cudaEventRecord(evJoin, side);

    // binning chain on main stream
    int vthreads = (n_edges + 3) / 4;
    hist_kernel<<<(vthreads + 255) / 256, 256>>>(dst, n_edges);
    scan1_kernel<<<(n_nodes + 255) / 256, 256>>>(n_nodes);
    perm_kernel<<<(vthreads + 255) / 256, 256>>>(src, dst, att, n_edges, nchunks, n_nodes);

    // join, then accumulate
    cudaStreamWaitEvent(0, evJoin, 0);
    long long work = (long long)n_nodes * 32;
    accum_kernel<<<(int)((work + 255) / 256), 256>>>(out, n_nodes);
}